// round 13
// baseline (speedup 1.0000x reference)
#include <cuda_runtime.h>
#include <cuda_bf16.h>
#include <cstdint>

// out[bt, i*16 + j] = x[bt, i] * W[i, j] + b[i, j]
// 256 MB fp32 write stream; measured device write ceiling ~5.3 TB/s sustained.
// Best-recorded-bench family = bulk-TMA stores (R4). This round: chunk = one
// bt row (8KB), double buffered (16KB smem) -> 8 blocks/SM instead of 7, more
// independent bulk-store groups in flight, balanced 148*8 grid.

#define C_IN   128
#define C_OUT  16
#define NBT    (64 * 512)
#define ROW_FLOATS 2048                 // one bt row of output
#define ROW_BYTES  (ROW_FLOATS * 4)     // 8192

#define NBLOCKS  (148 * 8)
#define NTHREADS 256

__device__ __forceinline__ uint32_t smem_u32(const void* p) {
    uint32_t a;
    asm("{ .reg .u64 t; cvta.to.shared.u64 t, %1; cvt.u32.u64 %0, t; }"
        : "=r"(a) : "l"(p));
    return a;
}

__global__ __launch_bounds__(NTHREADS, 8)
void real_embedding_tma_kernel(const float* __restrict__ x,
                               const float* __restrict__ W,
                               const float* __restrict__ b,
                               float* __restrict__ out)
{
    __shared__ __align__(128) float buf[2][ROW_FLOATS];

    const unsigned t = threadIdx.x;
    // Thread t owns output floats [t*8, t*8+8) of each row:
    //   i = t >> 1 (feature), h = t & 1 (which 8-output half).
    const unsigned h = t & 1u;
    const unsigned i = t >> 1;

    // Loop-invariant W/b slice in registers.
    const float4* W4 = (const float4*)(W + i * C_OUT + h * 8);
    const float4* B4 = (const float4*)(b + i * C_OUT + h * 8);
    const float4 w0 = W4[0], w1 = W4[1];
    const float4 c0 = B4[0], c1 = B4[1];

    unsigned iter = 0;
    for (unsigned bt = blockIdx.x; bt < NBT; bt += gridDim.x, iter++) {
        const unsigned p = iter & 1u;

        // Ensure the TMA that last read buffer p has finished reading it.
        if (t == 0 && iter >= 2) {
            asm volatile("cp.async.bulk.wait_group.read 1;" ::: "memory");
        }
        __syncthreads();

        const float xv = __ldg(x + (size_t)bt * C_IN + i);  // 2-way broadcast

        float4 o;
        o.x = fmaf(xv, w0.x, c0.x); o.y = fmaf(xv, w0.y, c0.y);
        o.z = fmaf(xv, w0.z, c0.z); o.w = fmaf(xv, w0.w, c0.w);
        *(float4*)&buf[p][t * 8] = o;
        o.x = fmaf(xv, w1.x, c1.x); o.y = fmaf(xv, w1.y, c1.y);
        o.z = fmaf(xv, w1.z, c1.z); o.w = fmaf(xv, w1.w, c1.w);
        *(float4*)&buf[p][t * 8 + 4] = o;

        __syncthreads();

        if (t == 0) {
            asm volatile("fence.proxy.async.shared::cta;" ::: "memory");
            const uint32_t src = smem_u32(&buf[p][0]);
            float* dst = out + (size_t)bt * ROW_FLOATS;
            asm volatile(
                "cp.async.bulk.global.shared::cta.bulk_group [%0], [%1], %2;"
                :: "l"(dst), "r"(src), "n"(ROW_BYTES) : "memory");
            asm volatile("cp.async.bulk.commit_group;" ::: "memory");
        }
    }

    // Drain all outstanding bulk stores before exit.
    if (t == 0) {
        asm volatile("cp.async.bulk.wait_group 0;" ::: "memory");
    }
}

extern "C" void kernel_launch(void* const* d_in, const int* in_sizes, int n_in,
                              void* d_out, int out_size) {
    const float* x = (const float*)d_in[0];
    const float* W = (const float*)d_in[1];
    const float* b = (const float*)d_in[2];
    float* out = (float*)d_out;

    (void)in_sizes; (void)n_in; (void)out_size;

    real_embedding_tma_kernel<<<NBLOCKS, NTHREADS>>>(x, W, b, out);
}